// round 15
// baseline (speedup 1.0000x reference)
#include <cuda_runtime.h>
#include <cuda_fp16.h>
#include <cstdint>

#define B_ 32
#define N_ 128
#define D_ 128
#define H_ 256
#define ROWS_ (B_ * N_)       // 4096
#define ST_ 264               // stride (halves) for K=256 tiles: 528B, mod128=16 -> conflict-free ldsm
#define ST1 136               // stride (halves) for K=128 tiles
#define NSM_ 148

// ---------------- scratch (device globals; no allocation allowed) ----------------
__device__ __half g_XI[ROWS_ * H_];      // receiver projection x@mw1[:D]
__device__ __half g_S [ROWS_ * H_];      // sender projection x@mw1[D:] + mb1
__device__ __half g_WT [D_ * H_];        // mw2^T: [d][h]
__device__ __half g_W1Ta[H_ * D_];       // mw1[:D]^T:  [h][k]
__device__ __half g_W1Tb[H_ * D_];       // mw1[D:]^T:  [h][k]
__device__ __half g_U1T[H_ * 2 * D_];    // uw1^T: [h][k] k=256
__device__ __half g_U2T[D_ * H_];        // uw2^T: [d][k] k=256
__device__ __half g_NH [ROWS_ * D_];     // nodes fp16 (written by k1)
__device__ float  g_AGGP[4 * ROWS_ * D_]; // per-jg aggregated partials (fp32)

// ---------------- helpers ----------------
__device__ __forceinline__ uint32_t smem_u32(const void* p) {
    return (uint32_t)__cvta_generic_to_shared(p);
}
__device__ __forceinline__ void cp16(void* s, const void* g) {
    asm volatile("cp.async.cg.shared.global [%0], [%1], 16;" :: "r"(smem_u32(s)), "l"(g));
}
__device__ __forceinline__ void cp_commit() {
    asm volatile("cp.async.commit_group;" ::: "memory");
}
template <int N>
__device__ __forceinline__ void cp_wait() {
    asm volatile("cp.async.wait_group %0;" :: "n"(N) : "memory");
}
__device__ __forceinline__ void ldsm_x4(uint32_t r[4], uint32_t addr) {
    asm volatile("ldmatrix.sync.aligned.m8n8.x4.shared.b16 {%0,%1,%2,%3}, [%4];"
                 : "=r"(r[0]), "=r"(r[1]), "=r"(r[2]), "=r"(r[3]) : "r"(addr));
}
__device__ __forceinline__ void mma16816(float c[4], const uint32_t a[4], uint32_t b0, uint32_t b1) {
    asm volatile("mma.sync.aligned.m16n8k16.row.col.f32.f16.f16.f32 "
                 "{%0,%1,%2,%3}, {%4,%5,%6,%7}, {%8,%9}, {%0,%1,%2,%3};"
                 : "+f"(c[0]), "+f"(c[1]), "+f"(c[2]), "+f"(c[3])
                 : "r"(a[0]), "r"(a[1]), "r"(a[2]), "r"(a[3]), "r"(b0), "r"(b1));
}

// ---------------- KW: coalesced tiled weight transposes ----------------
__global__ void kw(const float* __restrict__ mw1, const float* __restrict__ mw2,
                   const float* __restrict__ uw1, const float* __restrict__ uw2) {
    __shared__ float tile[32][33];
    int t = blockIdx.x, tid = threadIdx.x;
    const float* src; __half* dst; int srcLd, dstLd, tr, tc;
    if (t < 32)       { src = mw1;            dst = g_W1Ta; srcLd = 256; dstLd = 128; tr = t >> 3;  tc = t & 7; }
    else if (t < 64)  { t -= 32; src = mw1 + 128 * 256; dst = g_W1Tb; srcLd = 256; dstLd = 128; tr = t >> 3; tc = t & 7; }
    else if (t < 96)  { t -= 64; src = mw2;   dst = g_WT;   srcLd = 128; dstLd = 256; tr = t >> 2;  tc = t & 3; }
    else if (t < 160) { t -= 96; src = uw1;   dst = g_U1T;  srcLd = 256; dstLd = 256; tr = t >> 3;  tc = t & 7; }
    else              { t -= 160; src = uw2;  dst = g_U2T;  srcLd = 128; dstLd = 256; tr = t >> 2;  tc = t & 3; }
    int r0 = tr * 32, c0 = tc * 32;
    int lr = tid >> 3, lc = (tid & 7) * 4;
    float4 v = *(const float4*)&src[(size_t)(r0 + lr) * srcLd + c0 + lc];
    tile[lr][lc] = v.x; tile[lr][lc + 1] = v.y; tile[lr][lc + 2] = v.z; tile[lr][lc + 3] = v.w;
    __syncthreads();
    __half2 p0 = __floats2half2_rn(tile[lc][lr],     tile[lc + 1][lr]);
    __half2 p1 = __floats2half2_rn(tile[lc + 2][lr], tile[lc + 3][lr]);
    __half2* o = (__half2*)&dst[(size_t)(c0 + lr) * dstLd + r0 + lc];
    o[0] = p0; o[1] = p1;
}

// ---------------- K1: fused LayerNorm + mma projections (+ writes g_NH) ----------------
#define K1_XH 0
#define K1_BA 8704
#define K1_BB 78336
#define K1_TOT 147968
__global__ __launch_bounds__(256) void k1_proj(const float* __restrict__ nodes,
                                               const float* __restrict__ mask,
                                               const float* __restrict__ gam,
                                               const float* __restrict__ bet,
                                               const float* __restrict__ mb1) {
    extern __shared__ char sm1[];
    __half* xh = (__half*)(sm1 + K1_XH);
    __half* Ba = (__half*)(sm1 + K1_BA);
    __half* Bb = (__half*)(sm1 + K1_BB);
    int tid = threadIdx.x;
    int r0 = blockIdx.x * 32;
    int lane = tid & 31, w = tid >> 5;
    int isS = w >> 2, nq = w & 3, n0 = nq * 64;
    __half* Bsel = isS ? Bb : Ba;
    const __half* Bg = isS ? g_W1Tb : g_W1Ta;

    // each warp loads its own 64 weight rows (rows n0..n0+63)
    for (int e = lane; e < 1024; e += 32) {
        int r = n0 + (e >> 4), c = e & 15;
        cp16(&Bsel[r * ST1 + c * 8], &Bg[r * 128 + c * 8]);
    }
    cp_commit();

    {   // fused LayerNorm * mask -> xh (fp16); also nodes -> g_NH
        int row = tid >> 3, p = tid & 7;
        const float* np = &nodes[(size_t)(r0 + row) * D_ + p * 16];
        float4 v[4];
#pragma unroll
        for (int q = 0; q < 4; q++) v[q] = *(const float4*)&np[q * 4];
        float s = 0.f, s2 = 0.f;
#pragma unroll
        for (int q = 0; q < 4; q++) {
            s  += v[q].x + v[q].y + v[q].z + v[q].w;
            s2 += v[q].x*v[q].x + v[q].y*v[q].y + v[q].z*v[q].z + v[q].w*v[q].w;
        }
#pragma unroll
        for (int o = 1; o < 8; o <<= 1) {
            s  += __shfl_xor_sync(0xffffffffu, s,  o);
            s2 += __shfl_xor_sync(0xffffffffu, s2, o);
        }
        float mu  = s * (1.0f / 128.0f);
        float var = s2 * (1.0f / 128.0f) - mu * mu;
        float rs  = rsqrtf(var + 1e-5f);
        float m   = mask[r0 + row];
        __half* xo = &xh[row * ST1 + p * 16];
        const float* gp = &gam[p * 16];
        const float* bp = &bet[p * 16];
        const float* vv = (const float*)v;
        __half2* nh = (__half2*)&g_NH[(size_t)(r0 + row) * D_ + p * 16];
#pragma unroll
        for (int q = 0; q < 16; q++)
            xo[q] = __float2half(((vv[q] - mu) * rs * gp[q] + bp[q]) * m);
#pragma unroll
        for (int q = 0; q < 8; q++)
            nh[q] = __floats2half2_rn(vv[q * 2], vv[q * 2 + 1]);
    }
    cp_wait<0>();
    __syncthreads();

    uint32_t aB = smem_u32(&xh[(lane & 15) * ST1 + ((lane >> 4) & 1) * 8]);
    uint32_t bB = smem_u32(&Bsel[(n0 + (lane & 15)) * ST1 + ((lane >> 4) & 1) * 8]);

    float C[2][8][4] = {};
#pragma unroll
    for (int kt = 0; kt < 8; kt++) {
        uint32_t am[2][4], bf[4][4];
#pragma unroll
        for (int mt = 0; mt < 2; mt++) ldsm_x4(am[mt], aB + mt * (16 * ST1 * 2) + kt * 32);
#pragma unroll
        for (int q = 0; q < 4; q++) ldsm_x4(bf[q], bB + q * (16 * ST1 * 2) + kt * 32);
#pragma unroll
        for (int mt = 0; mt < 2; mt++)
#pragma unroll
            for (int q = 0; q < 4; q++) {
                mma16816(C[mt][q * 2],     am[mt], bf[q][0], bf[q][2]);
                mma16816(C[mt][q * 2 + 1], am[mt], bf[q][1], bf[q][3]);
            }
    }

    __half* dst = isS ? g_S : g_XI;
#pragma unroll
    for (int mt = 0; mt < 2; mt++) {
#pragma unroll
        for (int q = 0; q < 4; q++) {
#pragma unroll
            for (int sub = 0; sub < 2; sub++) {
                int nt = q * 2 + sub;
                int col = n0 + q * 16 + sub * 8 + (lane & 3) * 2;
                float b0 = 0.f, b1 = 0.f;
                if (isS) { b0 = mb1[col]; b1 = mb1[col + 1]; }
                int rowA = r0 + mt * 16 + (lane >> 2);
                *(__half2*)&dst[(size_t)rowA * H_ + col] =
                    __floats2half2_rn(C[mt][nt][0] + b0, C[mt][nt][1] + b1);
                *(__half2*)&dst[(size_t)(rowA + 8) * H_ + col] =
                    __floats2half2_rn(C[mt][nt][2] + b0, C[mt][nt][3] + b1);
            }
        }
    }
}

// ---------------- K2: persistent grid-148, 4-i units, S dbuf + prefetch, mma epilogue,
//                  per-jg partials straight to global (no combine barrier) ----------------
#define K2_W   0                          // 128 x 264 half (WT)             67584 B
#define K2_S   67584                      // 2 x 128 x 264 half (S dbuf)    135168 B
#define K2_X   202752                     // 2 x (4 x 256) half (xi dbuf)     4096 B
#define K2_MSK 206848                     // 2 x 128 float                    1024 B
#define K2_TOT 207872

__global__ __launch_bounds__(256, 1) void k2_main(const float* __restrict__ mb2,
                                                  const float* __restrict__ mask) {
    extern __shared__ char sm[];
    __half* wT  = (__half*)(sm + K2_W);
    __half* sS  = (__half*)(sm + K2_S);     // two buffers of 33792 halves, indexed by b&1
    __half* xiS = (__half*)(sm + K2_X);
    float*  mskJ = (float*)(sm + K2_MSK);   // two buffers of 128 floats

    int tid = threadIdx.x;
    int u0 = (blockIdx.x * 1024) / NSM_;
    int u1 = ((blockIdx.x + 1) * 1024) / NSM_;
    int b0 = u0 >> 5;

    // prologue group: WT + S(b0) + msk(b0) + xi(u0)
    for (int idx = tid; idx < 4096; idx += 256) {
        int r = idx >> 5, c = idx & 31;
        cp16(&wT[r * ST_ + c * 8], &g_WT[(size_t)r * H_ + c * 8]);
        cp16(&sS[(b0 & 1) * 33792 + r * ST_ + c * 8],
             &g_S[((size_t)(b0 * N_ + r)) * H_ + c * 8]);
    }
    if (tid < 32) cp16(&mskJ[(b0 & 1) * 128 + tid * 4], &mask[b0 * N_ + tid * 4]);
    if (tid < 128)
        cp16(&xiS[(u0 & 1) * 1024 + tid * 8],
             &g_XI[((size_t)(b0 * N_ + (u0 & 31) * 4)) * H_ + tid * 8]);
    cp_commit();

    int lane = tid & 31, w = tid >> 5;
    int mw = w & 1, jg = w >> 1;

    uint32_t aB = smem_u32(&wT[(mw * 64 + (lane & 15)) * ST_ + ((lane >> 4) & 1) * 8]);
    uint32_t bBbase = smem_u32(&sS[(jg * 32 + (lane & 15)) * ST_ + ((lane >> 4) & 1) * 8]);

    float bias[4][2];
#pragma unroll
    for (int mt = 0; mt < 4; mt++) {
        bias[mt][0] = mb2[mw * 64 + mt * 16 + (lane >> 2)];
        bias[mt][1] = mb2[mw * 64 + mt * 16 + (lane >> 2) + 8];
    }

    const __half2 z2 = __float2half2_rn(0.f);
    int curb = -1;
    uint32_t mbf[4];                      // mask B-fragments

    for (int u = u0; u < u1; u++) {
        int b = u >> 5, ic = u & 31;
        int sbuf = b & 1;
        bool bchg = (b != curb);

        // prefetch next unit's xi (+ next b's S/mask when crossing) into the other buffers
        int nu = u + 1;
        if (nu < u1) {
            int nb = nu >> 5;
            if (tid < 128)
                cp16(&xiS[(nu & 1) * 1024 + tid * 8],
                     &g_XI[((size_t)(nb * N_ + (nu & 31) * 4)) * H_ + tid * 8]);
            if (nb != b) {
                for (int idx = tid; idx < 4096; idx += 256) {
                    int r = idx >> 5, c = idx & 31;
                    cp16(&sS[(nb & 1) * 33792 + r * ST_ + c * 8],
                         &g_S[((size_t)(nb * N_ + r)) * H_ + c * 8]);
                }
                if (tid < 32) cp16(&mskJ[(nb & 1) * 128 + tid * 4], &mask[nb * N_ + tid * 4]);
            }
        }
        cp_commit();
        cp_wait<1>();                     // this unit's data complete; prefetch in flight
        __syncthreads();
        if (bchg) {
            int q2 = (lane & 3) * 2;
            int j0 = sbuf * 128 + jg * 32 + q2;
#pragma unroll
            for (int sgm = 0; sgm < 4; sgm++) {
                __half2 h = __floats2half2_rn(mskJ[j0 + sgm * 8], mskJ[j0 + sgm * 8 + 1]);
                mbf[sgm] = *(uint32_t*)&h;
            }
            curb = b;
        }
        const __half* xi = &xiS[(u & 1) * 1024];
        uint32_t bB = bBbase + sbuf * 67584;

        for (int ip = 0; ip < 2; ip++) {
            int i0 = ip * 2;
            float C[2][4][4][4] = {};      // [il][mt][nt][4]

            // pipelined kt loop: sf/x double-buffered one kt ahead
            uint32_t sf[2][2][4];
            __half2 xA[2][2], xB[2][2];
            ldsm_x4(sf[0][0], bB);
            ldsm_x4(sf[0][1], bB + 16 * ST_ * 2);
#pragma unroll
            for (int il = 0; il < 2; il++) {
                xA[0][il] = *(const __half2*)&xi[(i0 + il) * 256 + (lane & 3) * 2];
                xB[0][il] = *(const __half2*)&xi[(i0 + il) * 256 + (lane & 3) * 2 + 8];
            }
#pragma unroll
            for (int kt = 0; kt < 16; kt++) {
                const int cur = kt & 1, nxt = cur ^ 1;
                uint32_t A[4][4];
#pragma unroll
                for (int mt = 0; mt < 4; mt++)
                    ldsm_x4(A[mt], aB + mt * (16 * ST_ * 2) + kt * 32);
                if (kt < 15) {
                    ldsm_x4(sf[nxt][0], bB + (kt + 1) * 32);
                    ldsm_x4(sf[nxt][1], bB + 16 * ST_ * 2 + (kt + 1) * 32);
#pragma unroll
                    for (int il = 0; il < 2; il++) {
                        xA[nxt][il] = *(const __half2*)&xi[(i0 + il) * 256 + (kt + 1) * 16 + (lane & 3) * 2];
                        xB[nxt][il] = *(const __half2*)&xi[(i0 + il) * 256 + (kt + 1) * 16 + (lane & 3) * 2 + 8];
                    }
                }
#pragma unroll
                for (int il = 0; il < 2; il++) {
                    uint32_t bf[2][4];
#pragma unroll
                    for (int g = 0; g < 2; g++) {
                        __half2 t;
                        t = __hmax2(__hadd2(*(__half2*)&sf[cur][g][0], xA[cur][il]), z2); bf[g][0] = *(uint32_t*)&t;
                        t = __hmax2(__hadd2(*(__half2*)&sf[cur][g][1], xA[cur][il]), z2); bf[g][1] = *(uint32_t*)&t;
                        t = __hmax2(__hadd2(*(__half2*)&sf[cur][g][2], xB[cur][il]), z2); bf[g][2] = *(uint32_t*)&t;
                        t = __hmax2(__hadd2(*(__half2*)&sf[cur][g][3], xB[cur][il]), z2); bf[g][3] = *(uint32_t*)&t;
                    }
#pragma unroll
                    for (int mt = 0; mt < 4; mt++) {
                        mma16816(C[il][mt][0], A[mt], bf[0][0], bf[0][2]);
                        mma16816(C[il][mt][1], A[mt], bf[0][1], bf[0][3]);
                        mma16816(C[il][mt][2], A[mt], bf[1][0], bf[1][2]);
                        mma16816(C[il][mt][3], A[mt], bf[1][1], bf[1][3]);
                    }
                }
            }

            // epilogue: relu(+bias) -> fp16 A-fragments, j-reduce via mma, store to global
#pragma unroll
            for (int il = 0; il < 2; il++) {
#pragma unroll
                for (int mt = 0; mt < 4; mt++) {
                    float r2[4] = {0.f, 0.f, 0.f, 0.f};
#pragma unroll
                    for (int seg = 0; seg < 2; seg++) {
                        int nt0 = seg * 2;
                        uint32_t a[4];
                        __half2 h;
                        h = __floats2half2_rn(fmaxf(C[il][mt][nt0][0] + bias[mt][0], 0.f),
                                              fmaxf(C[il][mt][nt0][1] + bias[mt][0], 0.f));
                        a[0] = *(uint32_t*)&h;
                        h = __floats2half2_rn(fmaxf(C[il][mt][nt0][2] + bias[mt][1], 0.f),
                                              fmaxf(C[il][mt][nt0][3] + bias[mt][1], 0.f));
                        a[1] = *(uint32_t*)&h;
                        h = __floats2half2_rn(fmaxf(C[il][mt][nt0 + 1][0] + bias[mt][0], 0.f),
                                              fmaxf(C[il][mt][nt0 + 1][1] + bias[mt][0], 0.f));
                        a[2] = *(uint32_t*)&h;
                        h = __floats2half2_rn(fmaxf(C[il][mt][nt0 + 1][2] + bias[mt][1], 0.f),
                                              fmaxf(C[il][mt][nt0 + 1][3] + bias[mt][1], 0.f));
                        a[3] = *(uint32_t*)&h;
                        mma16816(r2, a, mbf[seg * 2], mbf[seg * 2 + 1]);
                    }
                    if ((lane & 3) == 0) {
                        int d = mw * 64 + mt * 16 + (lane >> 2);
                        size_t base = (size_t)jg * (ROWS_ * D_)
                                    + ((size_t)(b * N_ + ic * 4 + i0 + il)) * D_ + d;
                        g_AGGP[base]     = r2[0];
                        g_AGGP[base + 8] = r2[2];
                    }
                }
            }
        }
    }
}

// ---------------- K3: update MLP, 512 threads, partial-combine prologue; sU overlays sA ----------------
#define K3_A   0
#define K3_B1  16896
#define K3_B2  152064
#define K3_TOT 219648
__global__ __launch_bounds__(512) void k3_final(
    const float* __restrict__ nodes, const float* __restrict__ mask,
    const float* __restrict__ ub1, const float* __restrict__ ub2,
    float* __restrict__ out) {
    extern __shared__ char sm3[];
    __half* sA  = (__half*)(sm3 + K3_A);
    __half* sU  = (__half*)(sm3 + K3_A);
    __half* sB1 = (__half*)(sm3 + K3_B1);
    __half* sB2 = (__half*)(sm3 + K3_B2);
    int tid = threadIdx.x;
    int r0 = blockIdx.x * 32;

    // G0: nodes half of sA + U1T k-chunk0
    {
        int r = tid >> 4, c = tid & 15;
        cp16(&sA[r * ST_ + c * 8], &g_NH[((size_t)(r0 + r)) * D_ + c * 8]);
    }
    for (int idx = tid; idx < 4096; idx += 512) {
        int r = idx >> 4, c = idx & 15;
        cp16(&sB1[r * ST_ + c * 8], &g_U1T[r * 256 + c * 8]);
    }
    cp_commit();
    // G1: U1T k-chunk1
    for (int idx = tid; idx < 4096; idx += 512) {
        int r = idx >> 4, c = (idx & 15) + 16;
        cp16(&sB1[r * ST_ + c * 8], &g_U1T[r * 256 + c * 8]);
    }
    cp_commit();
    // G2: U2T
    for (int idx = tid; idx < 4096; idx += 512) {
        int r = idx >> 5, c = idx & 31;
        cp16(&sB2[r * ST_ + c * 8], &g_U2T[r * 256 + c * 8]);
    }
    cp_commit();

    // agg partial combine: LDG 4 per-jg partials, fp32 sum, fp16 -> sA cols 128..255
    {
        int rr = tid >> 4, dg = (tid & 15) * 8;
        size_t base = ((size_t)(r0 + rr)) * D_ + dg;
        const size_t STRIDE = (size_t)ROWS_ * D_;
        float4 p[4][2];
#pragma unroll
        for (int j = 0; j < 4; j++) {
            p[j][0] = *(const float4*)&g_AGGP[j * STRIDE + base];
            p[j][1] = *(const float4*)&g_AGGP[j * STRIDE + base + 4];
        }
        float v[8];
        v[0] = p[0][0].x + p[1][0].x + p[2][0].x + p[3][0].x;
        v[1] = p[0][0].y + p[1][0].y + p[2][0].y + p[3][0].y;
        v[2] = p[0][0].z + p[1][0].z + p[2][0].z + p[3][0].z;
        v[3] = p[0][0].w + p[1][0].w + p[2][0].w + p[3][0].w;
        v[4] = p[0][1].x + p[1][1].x + p[2][1].x + p[3][1].x;
        v[5] = p[0][1].y + p[1][1].y + p[2][1].y + p[3][1].y;
        v[6] = p[0][1].z + p[1][1].z + p[2][1].z + p[3][1].z;
        v[7] = p[0][1].w + p[1][1].w + p[2][1].w + p[3][1].w;
        __half2* ap = (__half2*)&sA[rr * ST_ + 128 + dg];
        ap[0] = __floats2half2_rn(v[0], v[1]);
        ap[1] = __floats2half2_rn(v[2], v[3]);
        ap[2] = __floats2half2_rn(v[4], v[5]);
        ap[3] = __floats2half2_rn(v[6], v[7]);
    }

    int lane = tid & 31, w = tid >> 5;
    int mg = w >> 3, nq = w & 7;

    cp_wait<2>();
    __syncthreads();

    // ---- stage 1: u = relu([nodes|agg] @ uw1 + ub1); 8 nq x 32 cols ----
    float C[4][4] = {};
    {
        int n0 = nq * 32;
        uint32_t aB = smem_u32(&sA[(mg * 16 + (lane & 15)) * ST_ + ((lane >> 4) & 1) * 8]);
        uint32_t bB = smem_u32(&sB1[(n0 + (lane & 15)) * ST_ + ((lane >> 4) & 1) * 8]);
#pragma unroll
        for (int kt = 0; kt < 8; kt++) {
            uint32_t am[4], bf0[4], bf1[4];
            ldsm_x4(am, aB + kt * 32);
            ldsm_x4(bf0, bB + kt * 32);
            ldsm_x4(bf1, bB + 16 * ST_ * 2 + kt * 32);
            mma16816(C[0], am, bf0[0], bf0[2]);
            mma16816(C[1], am, bf0[1], bf0[3]);
            mma16816(C[2], am, bf1[0], bf1[2]);
            mma16816(C[3], am, bf1[1], bf1[3]);
        }
        cp_wait<1>();
        __syncthreads();
#pragma unroll
        for (int kt = 8; kt < 16; kt++) {
            uint32_t am[4], bf0[4], bf1[4];
            ldsm_x4(am, aB + kt * 32);
            ldsm_x4(bf0, bB + kt * 32);
            ldsm_x4(bf1, bB + 16 * ST_ * 2 + kt * 32);
            mma16816(C[0], am, bf0[0], bf0[2]);
            mma16816(C[1], am, bf0[1], bf0[3]);
            mma16816(C[2], am, bf1[0], bf1[2]);
            mma16816(C[3], am, bf1[1], bf1[3]);
        }
    }
    __syncthreads();       // all sA reads done before overlay write
    {
        int n0 = nq * 32;
#pragma unroll
        for (int q = 0; q < 2; q++) {
#pragma unroll
            for (int sub = 0; sub < 2; sub++) {
                int nt = q * 2 + sub;
                int col = n0 + q * 16 + sub * 8 + (lane & 3) * 2;
                float b0 = ub1[col], b1 = ub1[col + 1];
                int rowl = mg * 16 + (lane >> 2);
                *(__half2*)&sU[rowl * ST_ + col] =
                    __floats2half2_rn(fmaxf(C[nt][0] + b0, 0.f), fmaxf(C[nt][1] + b1, 0.f));
                *(__half2*)&sU[(rowl + 8) * ST_ + col] =
                    __floats2half2_rn(fmaxf(C[nt][2] + b0, 0.f), fmaxf(C[nt][3] + b1, 0.f));
            }
        }
    }
    cp_wait<0>();
    __syncthreads();

    // ---- stage 2: out = (nodes + u @ uw2 + ub2) * mask; 8 nq x 16 cols ----
    {
        int n0 = nq * 16;
        uint32_t aB = smem_u32(&sU[(mg * 16 + (lane & 15)) * ST_ + ((lane >> 4) & 1) * 8]);
        uint32_t bB = smem_u32(&sB2[(n0 + (lane & 15)) * ST_ + ((lane >> 4) & 1) * 8]);
        float C2[2][4] = {};
#pragma unroll
        for (int kt = 0; kt < 16; kt++) {
            uint32_t am[4], bf[4];
            ldsm_x4(am, aB + kt * 32);
            ldsm_x4(bf, bB + kt * 32);
            mma16816(C2[0], am, bf[0], bf[2]);
            mma16816(C2[1], am, bf[1], bf[3]);
        }
        int rowA = r0 + mg * 16 + (lane >> 2);
        float mk0 = mask[rowA], mk1 = mask[rowA + 8];
#pragma unroll
        for (int sub = 0; sub < 2; sub++) {
            int col = n0 + sub * 8 + (lane & 3) * 2;
            float b0 = ub2[col], b1 = ub2[col + 1];
            const float2 nv0 = *(const float2*)&nodes[(size_t)rowA * D_ + col];
            const float2 nv1 = *(const float2*)&nodes[(size_t)(rowA + 8) * D_ + col];
            float2 o0, o1;
            o0.x = (nv0.x + C2[sub][0] + b0) * mk0;
            o0.y = (nv0.y + C2[sub][1] + b1) * mk0;
            o1.x = (nv1.x + C2[sub][2] + b0) * mk1;
            o1.y = (nv1.y + C2[sub][3] + b1) * mk1;
            *(float2*)&out[(size_t)rowA * D_ + col]       = o0;
            *(float2*)&out[(size_t)(rowA + 8) * D_ + col] = o1;
        }
    }
}

// ---------------- launch ----------------
extern "C" void kernel_launch(void* const* d_in, const int* in_sizes, int n_in,
                              void* d_out, int out_size) {
    const float* nodes = (const float*)d_in[0];
    const float* mask  = (const float*)d_in[1];
    const float* ln_g  = (const float*)d_in[2];
    const float* ln_b  = (const float*)d_in[3];
    const float* mw1   = (const float*)d_in[4];
    const float* mb1   = (const float*)d_in[5];
    const float* mw2   = (const float*)d_in[6];
    const float* mb2   = (const float*)d_in[7];
    const float* uw1   = (const float*)d_in[8];
    const float* ub1   = (const float*)d_in[9];
    const float* uw2   = (const float*)d_in[10];
    const float* ub2   = (const float*)d_in[11];
    float* out = (float*)d_out;

    cudaFuncSetAttribute(k1_proj,  cudaFuncAttributeMaxDynamicSharedMemorySize, K1_TOT);
    cudaFuncSetAttribute(k2_main,  cudaFuncAttributeMaxDynamicSharedMemorySize, K2_TOT);
    cudaFuncSetAttribute(k3_final, cudaFuncAttributeMaxDynamicSharedMemorySize, K3_TOT);

    kw<<<192, 256>>>(mw1, mw2, uw1, uw2);
    k1_proj<<<128, 256, K1_TOT>>>(nodes, mask, ln_g, ln_b, mb1);
    k2_main<<<NSM_, 256, K2_TOT>>>(mb2, mask);
    k3_final<<<128, 512, K3_TOT>>>(nodes, mask, ub1, ub2, out);
}

// round 16
// speedup vs baseline: 1.0240x; 1.0240x over previous
#include <cuda_runtime.h>
#include <cuda_fp16.h>
#include <cstdint>

#define B_ 32
#define N_ 128
#define D_ 128
#define H_ 256
#define ROWS_ (B_ * N_)       // 4096
#define ST_ 264               // stride (halves) for K=256 tiles: 528B, mod128=16 -> conflict-free ldsm
#define ST1 136               // stride (halves) for K=128 tiles
#define NSM_ 148

// ---------------- scratch (device globals; no allocation allowed) ----------------
__device__ __half g_XI[ROWS_ * H_];      // receiver projection x@mw1[:D]
__device__ __half g_S [ROWS_ * H_];      // sender projection x@mw1[D:] + mb1
__device__ __half g_WT [D_ * H_];        // mw2^T: [d][h]
__device__ __half g_W1Ta[H_ * D_];       // mw1[:D]^T:  [h][k]
__device__ __half g_W1Tb[H_ * D_];       // mw1[D:]^T:  [h][k]
__device__ __half g_U1T[H_ * 2 * D_];    // uw1^T: [h][k] k=256
__device__ __half g_U2T[D_ * H_];        // uw2^T: [d][k] k=256
__device__ __half g_NH [ROWS_ * D_];     // nodes fp16 (written by k1)
__device__ __half g_AGGH[ROWS_ * D_];    // aggregated messages fp16

// ---------------- helpers ----------------
__device__ __forceinline__ uint32_t smem_u32(const void* p) {
    return (uint32_t)__cvta_generic_to_shared(p);
}
__device__ __forceinline__ void cp16(void* s, const void* g) {
    asm volatile("cp.async.cg.shared.global [%0], [%1], 16;" :: "r"(smem_u32(s)), "l"(g));
}
__device__ __forceinline__ void cp_commit() {
    asm volatile("cp.async.commit_group;" ::: "memory");
}
template <int N>
__device__ __forceinline__ void cp_wait() {
    asm volatile("cp.async.wait_group %0;" :: "n"(N) : "memory");
}
__device__ __forceinline__ void ldsm_x4(uint32_t r[4], uint32_t addr) {
    asm volatile("ldmatrix.sync.aligned.m8n8.x4.shared.b16 {%0,%1,%2,%3}, [%4];"
                 : "=r"(r[0]), "=r"(r[1]), "=r"(r[2]), "=r"(r[3]) : "r"(addr));
}
__device__ __forceinline__ void mma16816(float c[4], const uint32_t a[4], uint32_t b0, uint32_t b1) {
    asm volatile("mma.sync.aligned.m16n8k16.row.col.f32.f16.f16.f32 "
                 "{%0,%1,%2,%3}, {%4,%5,%6,%7}, {%8,%9}, {%0,%1,%2,%3};"
                 : "+f"(c[0]), "+f"(c[1]), "+f"(c[2]), "+f"(c[3])
                 : "r"(a[0]), "r"(a[1]), "r"(a[2]), "r"(a[3]), "r"(b0), "r"(b1));
}

// ---------------- KW: coalesced tiled weight transposes ----------------
__global__ void kw(const float* __restrict__ mw1, const float* __restrict__ mw2,
                   const float* __restrict__ uw1, const float* __restrict__ uw2) {
    __shared__ float tile[32][33];
    int t = blockIdx.x, tid = threadIdx.x;
    const float* src; __half* dst; int srcLd, dstLd, tr, tc;
    if (t < 32)       { src = mw1;            dst = g_W1Ta; srcLd = 256; dstLd = 128; tr = t >> 3;  tc = t & 7; }
    else if (t < 64)  { t -= 32; src = mw1 + 128 * 256; dst = g_W1Tb; srcLd = 256; dstLd = 128; tr = t >> 3; tc = t & 7; }
    else if (t < 96)  { t -= 64; src = mw2;   dst = g_WT;   srcLd = 128; dstLd = 256; tr = t >> 2;  tc = t & 3; }
    else if (t < 160) { t -= 96; src = uw1;   dst = g_U1T;  srcLd = 256; dstLd = 256; tr = t >> 3;  tc = t & 7; }
    else              { t -= 160; src = uw2;  dst = g_U2T;  srcLd = 128; dstLd = 256; tr = t >> 2;  tc = t & 3; }
    int r0 = tr * 32, c0 = tc * 32;
    int lr = tid >> 3, lc = (tid & 7) * 4;
    float4 v = *(const float4*)&src[(size_t)(r0 + lr) * srcLd + c0 + lc];
    tile[lr][lc] = v.x; tile[lr][lc + 1] = v.y; tile[lr][lc + 2] = v.z; tile[lr][lc + 3] = v.w;
    __syncthreads();
    __half2 p0 = __floats2half2_rn(tile[lc][lr],     tile[lc + 1][lr]);
    __half2 p1 = __floats2half2_rn(tile[lc + 2][lr], tile[lc + 3][lr]);
    __half2* o = (__half2*)&dst[(size_t)(c0 + lr) * dstLd + r0 + lc];
    o[0] = p0; o[1] = p1;
}

// ---------------- K1: fused LayerNorm + mma projections (+ writes g_NH) ----------------
#define K1_XH 0
#define K1_BA 8704
#define K1_BB 78336
#define K1_TOT 147968
__global__ __launch_bounds__(256) void k1_proj(const float* __restrict__ nodes,
                                               const float* __restrict__ mask,
                                               const float* __restrict__ gam,
                                               const float* __restrict__ bet,
                                               const float* __restrict__ mb1) {
    extern __shared__ char sm1[];
    __half* xh = (__half*)(sm1 + K1_XH);
    __half* Ba = (__half*)(sm1 + K1_BA);
    __half* Bb = (__half*)(sm1 + K1_BB);
    int tid = threadIdx.x;
    int r0 = blockIdx.x * 32;
    int lane = tid & 31, w = tid >> 5;
    int isS = w >> 2, nq = w & 3, n0 = nq * 64;
    __half* Bsel = isS ? Bb : Ba;
    const __half* Bg = isS ? g_W1Tb : g_W1Ta;

    // each warp loads its own 64 weight rows (rows n0..n0+63)
    for (int e = lane; e < 1024; e += 32) {
        int r = n0 + (e >> 4), c = e & 15;
        cp16(&Bsel[r * ST1 + c * 8], &Bg[r * 128 + c * 8]);
    }
    cp_commit();

    {   // fused LayerNorm * mask -> xh (fp16); also nodes -> g_NH
        int row = tid >> 3, p = tid & 7;
        const float* np = &nodes[(size_t)(r0 + row) * D_ + p * 16];
        float4 v[4];
#pragma unroll
        for (int q = 0; q < 4; q++) v[q] = *(const float4*)&np[q * 4];
        float s = 0.f, s2 = 0.f;
#pragma unroll
        for (int q = 0; q < 4; q++) {
            s  += v[q].x + v[q].y + v[q].z + v[q].w;
            s2 += v[q].x*v[q].x + v[q].y*v[q].y + v[q].z*v[q].z + v[q].w*v[q].w;
        }
#pragma unroll
        for (int o = 1; o < 8; o <<= 1) {
            s  += __shfl_xor_sync(0xffffffffu, s,  o);
            s2 += __shfl_xor_sync(0xffffffffu, s2, o);
        }
        float mu  = s * (1.0f / 128.0f);
        float var = s2 * (1.0f / 128.0f) - mu * mu;
        float rs  = rsqrtf(var + 1e-5f);
        float m   = mask[r0 + row];
        __half* xo = &xh[row * ST1 + p * 16];
        const float* gp = &gam[p * 16];
        const float* bp = &bet[p * 16];
        const float* vv = (const float*)v;
        __half2* nh = (__half2*)&g_NH[(size_t)(r0 + row) * D_ + p * 16];
#pragma unroll
        for (int q = 0; q < 16; q++)
            xo[q] = __float2half(((vv[q] - mu) * rs * gp[q] + bp[q]) * m);
#pragma unroll
        for (int q = 0; q < 8; q++)
            nh[q] = __floats2half2_rn(vv[q * 2], vv[q * 2 + 1]);
    }
    cp_wait<0>();
    __syncthreads();

    uint32_t aB = smem_u32(&xh[(lane & 15) * ST1 + ((lane >> 4) & 1) * 8]);
    uint32_t bB = smem_u32(&Bsel[(n0 + (lane & 15)) * ST1 + ((lane >> 4) & 1) * 8]);

    float C[2][8][4] = {};
#pragma unroll
    for (int kt = 0; kt < 8; kt++) {
        uint32_t am[2][4], bf[4][4];
#pragma unroll
        for (int mt = 0; mt < 2; mt++) ldsm_x4(am[mt], aB + mt * (16 * ST1 * 2) + kt * 32);
#pragma unroll
        for (int q = 0; q < 4; q++) ldsm_x4(bf[q], bB + q * (16 * ST1 * 2) + kt * 32);
#pragma unroll
        for (int mt = 0; mt < 2; mt++)
#pragma unroll
            for (int q = 0; q < 4; q++) {
                mma16816(C[mt][q * 2],     am[mt], bf[q][0], bf[q][2]);
                mma16816(C[mt][q * 2 + 1], am[mt], bf[q][1], bf[q][3]);
            }
    }

    __half* dst = isS ? g_S : g_XI;
#pragma unroll
    for (int mt = 0; mt < 2; mt++) {
#pragma unroll
        for (int q = 0; q < 4; q++) {
#pragma unroll
            for (int sub = 0; sub < 2; sub++) {
                int nt = q * 2 + sub;
                int col = n0 + q * 16 + sub * 8 + (lane & 3) * 2;
                float b0 = 0.f, b1 = 0.f;
                if (isS) { b0 = mb1[col]; b1 = mb1[col + 1]; }
                int rowA = r0 + mt * 16 + (lane >> 2);
                *(__half2*)&dst[(size_t)rowA * H_ + col] =
                    __floats2half2_rn(C[mt][nt][0] + b0, C[mt][nt][1] + b1);
                *(__half2*)&dst[(size_t)(rowA + 8) * H_ + col] =
                    __floats2half2_rn(C[mt][nt][2] + b0, C[mt][nt][3] + b1);
            }
        }
    }
}

// ---------------- K2: persistent grid-148, 4-i units, S dbuf + prefetch, mma epilogue ----------------
// (round-14 version: smem part buffer + combine, fp16 g_AGGH output)
#define K2_W   0                          // 128 x 264 half (WT)             67584 B
#define K2_S   67584                      // 2 x 128 x 264 half (S dbuf)    135168 B
#define K2_X   202752                     // 2 x (4 x 256) half (xi dbuf)     4096 B
#define K2_P   206848                     // part[16][128] float              8192 B
#define K2_MSK 215040                     // 2 x 128 float                    1024 B
#define K2_TOT 216064

__global__ __launch_bounds__(256, 1) void k2_main(const float* __restrict__ mb2,
                                                  const float* __restrict__ mask) {
    extern __shared__ char sm[];
    __half* wT  = (__half*)(sm + K2_W);
    __half* sS  = (__half*)(sm + K2_S);     // two buffers of 33792 halves, indexed by b&1
    __half* xiS = (__half*)(sm + K2_X);
    float*  part = (float*)(sm + K2_P);
    float*  mskJ = (float*)(sm + K2_MSK);   // two buffers of 128 floats

    int tid = threadIdx.x;
    int u0 = (blockIdx.x * 1024) / NSM_;
    int u1 = ((blockIdx.x + 1) * 1024) / NSM_;
    int b0 = u0 >> 5;

    // prologue group: WT + S(b0) + msk(b0) + xi(u0)
    for (int idx = tid; idx < 4096; idx += 256) {
        int r = idx >> 5, c = idx & 31;
        cp16(&wT[r * ST_ + c * 8], &g_WT[(size_t)r * H_ + c * 8]);
        cp16(&sS[(b0 & 1) * 33792 + r * ST_ + c * 8],
             &g_S[((size_t)(b0 * N_ + r)) * H_ + c * 8]);
    }
    if (tid < 32) cp16(&mskJ[(b0 & 1) * 128 + tid * 4], &mask[b0 * N_ + tid * 4]);
    if (tid < 128)
        cp16(&xiS[(u0 & 1) * 1024 + tid * 8],
             &g_XI[((size_t)(b0 * N_ + (u0 & 31) * 4)) * H_ + tid * 8]);
    cp_commit();

    int lane = tid & 31, w = tid >> 5;
    int mw = w & 1, jg = w >> 1;

    uint32_t aB = smem_u32(&wT[(mw * 64 + (lane & 15)) * ST_ + ((lane >> 4) & 1) * 8]);
    uint32_t bBbase = smem_u32(&sS[(jg * 32 + (lane & 15)) * ST_ + ((lane >> 4) & 1) * 8]);

    float bias[4][2];
#pragma unroll
    for (int mt = 0; mt < 4; mt++) {
        bias[mt][0] = mb2[mw * 64 + mt * 16 + (lane >> 2)];
        bias[mt][1] = mb2[mw * 64 + mt * 16 + (lane >> 2) + 8];
    }

    const __half2 z2 = __float2half2_rn(0.f);
    int curb = -1;
    uint32_t mbf[4];                      // mask B-fragments

    for (int u = u0; u < u1; u++) {
        int b = u >> 5, ic = u & 31;
        int sbuf = b & 1;
        bool bchg = (b != curb);

        // prefetch next unit's xi (+ next b's S/mask when crossing) into the other buffers
        int nu = u + 1;
        if (nu < u1) {
            int nb = nu >> 5;
            if (tid < 128)
                cp16(&xiS[(nu & 1) * 1024 + tid * 8],
                     &g_XI[((size_t)(nb * N_ + (nu & 31) * 4)) * H_ + tid * 8]);
            if (nb != b) {
                for (int idx = tid; idx < 4096; idx += 256) {
                    int r = idx >> 5, c = idx & 31;
                    cp16(&sS[(nb & 1) * 33792 + r * ST_ + c * 8],
                         &g_S[((size_t)(nb * N_ + r)) * H_ + c * 8]);
                }
                if (tid < 32) cp16(&mskJ[(nb & 1) * 128 + tid * 4], &mask[nb * N_ + tid * 4]);
            }
        }
        cp_commit();
        cp_wait<1>();                     // this unit's data complete; prefetch in flight
        __syncthreads();
        if (bchg) {
            int q2 = (lane & 3) * 2;
            int j0 = sbuf * 128 + jg * 32 + q2;
#pragma unroll
            for (int sgm = 0; sgm < 4; sgm++) {
                __half2 h = __floats2half2_rn(mskJ[j0 + sgm * 8], mskJ[j0 + sgm * 8 + 1]);
                mbf[sgm] = *(uint32_t*)&h;
            }
            curb = b;
        }
        const __half* xi = &xiS[(u & 1) * 1024];
        uint32_t bB = bBbase + sbuf * 67584;

        for (int ip = 0; ip < 2; ip++) {
            int i0 = ip * 2;
            float C[2][4][4][4] = {};      // [il][mt][nt][4]

            // pipelined kt loop: sf/x double-buffered one kt ahead
            uint32_t sf[2][2][4];
            __half2 xA[2][2], xB[2][2];
            ldsm_x4(sf[0][0], bB);
            ldsm_x4(sf[0][1], bB + 16 * ST_ * 2);
#pragma unroll
            for (int il = 0; il < 2; il++) {
                xA[0][il] = *(const __half2*)&xi[(i0 + il) * 256 + (lane & 3) * 2];
                xB[0][il] = *(const __half2*)&xi[(i0 + il) * 256 + (lane & 3) * 2 + 8];
            }
#pragma unroll
            for (int kt = 0; kt < 16; kt++) {
                const int cur = kt & 1, nxt = cur ^ 1;
                uint32_t A[4][4];
#pragma unroll
                for (int mt = 0; mt < 4; mt++)
                    ldsm_x4(A[mt], aB + mt * (16 * ST_ * 2) + kt * 32);
                if (kt < 15) {
                    ldsm_x4(sf[nxt][0], bB + (kt + 1) * 32);
                    ldsm_x4(sf[nxt][1], bB + 16 * ST_ * 2 + (kt + 1) * 32);
#pragma unroll
                    for (int il = 0; il < 2; il++) {
                        xA[nxt][il] = *(const __half2*)&xi[(i0 + il) * 256 + (kt + 1) * 16 + (lane & 3) * 2];
                        xB[nxt][il] = *(const __half2*)&xi[(i0 + il) * 256 + (kt + 1) * 16 + (lane & 3) * 2 + 8];
                    }
                }
#pragma unroll
                for (int il = 0; il < 2; il++) {
                    uint32_t bf[2][4];
#pragma unroll
                    for (int g = 0; g < 2; g++) {
                        __half2 t;
                        t = __hmax2(__hadd2(*(__half2*)&sf[cur][g][0], xA[cur][il]), z2); bf[g][0] = *(uint32_t*)&t;
                        t = __hmax2(__hadd2(*(__half2*)&sf[cur][g][1], xA[cur][il]), z2); bf[g][1] = *(uint32_t*)&t;
                        t = __hmax2(__hadd2(*(__half2*)&sf[cur][g][2], xB[cur][il]), z2); bf[g][2] = *(uint32_t*)&t;
                        t = __hmax2(__hadd2(*(__half2*)&sf[cur][g][3], xB[cur][il]), z2); bf[g][3] = *(uint32_t*)&t;
                    }
#pragma unroll
                    for (int mt = 0; mt < 4; mt++) {
                        mma16816(C[il][mt][0], A[mt], bf[0][0], bf[0][2]);
                        mma16816(C[il][mt][1], A[mt], bf[0][1], bf[0][3]);
                        mma16816(C[il][mt][2], A[mt], bf[1][0], bf[1][2]);
                        mma16816(C[il][mt][3], A[mt], bf[1][1], bf[1][3]);
                    }
                }
            }

            // epilogue: relu(+bias) -> fp16 A-fragments, j-reduce via mma with mask B-fragment
#pragma unroll
            for (int il = 0; il < 2; il++) {
#pragma unroll
                for (int mt = 0; mt < 4; mt++) {
                    float r2[4] = {0.f, 0.f, 0.f, 0.f};
#pragma unroll
                    for (int seg = 0; seg < 2; seg++) {
                        int nt0 = seg * 2;
                        uint32_t a[4];
                        __half2 h;
                        h = __floats2half2_rn(fmaxf(C[il][mt][nt0][0] + bias[mt][0], 0.f),
                                              fmaxf(C[il][mt][nt0][1] + bias[mt][0], 0.f));
                        a[0] = *(uint32_t*)&h;
                        h = __floats2half2_rn(fmaxf(C[il][mt][nt0][2] + bias[mt][1], 0.f),
                                              fmaxf(C[il][mt][nt0][3] + bias[mt][1], 0.f));
                        a[1] = *(uint32_t*)&h;
                        h = __floats2half2_rn(fmaxf(C[il][mt][nt0 + 1][0] + bias[mt][0], 0.f),
                                              fmaxf(C[il][mt][nt0 + 1][1] + bias[mt][0], 0.f));
                        a[2] = *(uint32_t*)&h;
                        h = __floats2half2_rn(fmaxf(C[il][mt][nt0 + 1][2] + bias[mt][1], 0.f),
                                              fmaxf(C[il][mt][nt0 + 1][3] + bias[mt][1], 0.f));
                        a[3] = *(uint32_t*)&h;
                        mma16816(r2, a, mbf[seg * 2], mbf[seg * 2 + 1]);
                    }
                    if ((lane & 3) == 0) {
                        int d = mw * 64 + mt * 16 + (lane >> 2);
                        part[(jg * 4 + i0 + il) * 128 + d]     = r2[0];
                        part[(jg * 4 + i0 + il) * 128 + d + 8] = r2[2];
                    }
                }
            }
        }
        __syncthreads();                  // all partials written
        {
            int i4 = tid >> 6, dp = (tid & 63) * 2;
            float v0 = part[i4 * 128 + dp]     + part[(4 + i4) * 128 + dp]
                     + part[(8 + i4) * 128 + dp]     + part[(12 + i4) * 128 + dp];
            float v1 = part[i4 * 128 + dp + 1] + part[(4 + i4) * 128 + dp + 1]
                     + part[(8 + i4) * 128 + dp + 1] + part[(12 + i4) * 128 + dp + 1];
            *(__half2*)&g_AGGH[((size_t)(b * N_ + ic * 4 + i4)) * D_ + dp] =
                __floats2half2_rn(v0, v1);
        }
    }
}

// ---------------- K3: update MLP, 512 threads (2mg x 8nq), pipelined loads; sU overlays sA ----------------
#define K3_A   0
#define K3_B1  16896
#define K3_B2  152064
#define K3_TOT 219648
__global__ __launch_bounds__(512) void k3_final(
    const float* __restrict__ nodes, const float* __restrict__ mask,
    const float* __restrict__ ub1, const float* __restrict__ ub2,
    float* __restrict__ out) {
    extern __shared__ char sm3[];
    __half* sA  = (__half*)(sm3 + K3_A);
    __half* sU  = (__half*)(sm3 + K3_A);
    __half* sB1 = (__half*)(sm3 + K3_B1);
    __half* sB2 = (__half*)(sm3 + K3_B2);
    int tid = threadIdx.x;
    int r0 = blockIdx.x * 32;

    // G0: activations ([nodes_h | agg_h]) + U1T k-chunk0
    for (int idx = tid; idx < 1024; idx += 512) {
        int r = idx >> 5, c = idx & 31;
        const __half* src = (c < 16) ? &g_NH[((size_t)(r0 + r)) * D_ + c * 8]
                                     : &g_AGGH[((size_t)(r0 + r)) * D_ + (c - 16) * 8];
        cp16(&sA[r * ST_ + c * 8], src);
    }
    for (int idx = tid; idx < 4096; idx += 512) {
        int r = idx >> 4, c = idx & 15;
        cp16(&sB1[r * ST_ + c * 8], &g_U1T[r * 256 + c * 8]);
    }
    cp_commit();
    // G1: U1T k-chunk1
    for (int idx = tid; idx < 4096; idx += 512) {
        int r = idx >> 4, c = (idx & 15) + 16;
        cp16(&sB1[r * ST_ + c * 8], &g_U1T[r * 256 + c * 8]);
    }
    cp_commit();
    // G2: U2T
    for (int idx = tid; idx < 4096; idx += 512) {
        int r = idx >> 5, c = idx & 31;
        cp16(&sB2[r * ST_ + c * 8], &g_U2T[r * 256 + c * 8]);
    }
    cp_commit();

    int lane = tid & 31, w = tid >> 5;
    int mg = w >> 3, nq = w & 7;

    cp_wait<2>();
    __syncthreads();

    // ---- stage 1: u = relu([nodes|agg] @ uw1 + ub1); 8 nq x 32 cols ----
    float C[4][4] = {};
    {
        int n0 = nq * 32;
        uint32_t aB = smem_u32(&sA[(mg * 16 + (lane & 15)) * ST_ + ((lane >> 4) & 1) * 8]);
        uint32_t bB = smem_u32(&sB1[(n0 + (lane & 15)) * ST_ + ((lane >> 4) & 1) * 8]);
#pragma unroll
        for (int kt = 0; kt < 8; kt++) {
            uint32_t am[4], bf0[4], bf1[4];
            ldsm_x4(am, aB + kt * 32);
            ldsm_x4(bf0, bB + kt * 32);
            ldsm_x4(bf1, bB + 16 * ST_ * 2 + kt * 32);
            mma16816(C[0], am, bf0[0], bf0[2]);
            mma16816(C[1], am, bf0[1], bf0[3]);
            mma16816(C[2], am, bf1[0], bf1[2]);
            mma16816(C[3], am, bf1[1], bf1[3]);
        }
        cp_wait<1>();
        __syncthreads();
#pragma unroll
        for (int kt = 8; kt < 16; kt++) {
            uint32_t am[4], bf0[4], bf1[4];
            ldsm_x4(am, aB + kt * 32);
            ldsm_x4(bf0, bB + kt * 32);
            ldsm_x4(bf1, bB + 16 * ST_ * 2 + kt * 32);
            mma16816(C[0], am, bf0[0], bf0[2]);
            mma16816(C[1], am, bf0[1], bf0[3]);
            mma16816(C[2], am, bf1[0], bf1[2]);
            mma16816(C[3], am, bf1[1], bf1[3]);
        }
    }
    __syncthreads();       // all sA reads done before overlay write
    {
        int n0 = nq * 32;
#pragma unroll
        for (int q = 0; q < 2; q++) {
#pragma unroll
            for (int sub = 0; sub < 2; sub++) {
                int nt = q * 2 + sub;
                int col = n0 + q * 16 + sub * 8 + (lane & 3) * 2;
                float b0 = ub1[col], b1 = ub1[col + 1];
                int rowl = mg * 16 + (lane >> 2);
                *(__half2*)&sU[rowl * ST_ + col] =
                    __floats2half2_rn(fmaxf(C[nt][0] + b0, 0.f), fmaxf(C[nt][1] + b1, 0.f));
                *(__half2*)&sU[(rowl + 8) * ST_ + col] =
                    __floats2half2_rn(fmaxf(C[nt][2] + b0, 0.f), fmaxf(C[nt][3] + b1, 0.f));
            }
        }
    }
    cp_wait<0>();
    __syncthreads();

    // ---- stage 2: out = (nodes + u @ uw2 + ub2) * mask; 8 nq x 16 cols ----
    {
        int n0 = nq * 16;
        uint32_t aB = smem_u32(&sU[(mg * 16 + (lane & 15)) * ST_ + ((lane >> 4) & 1) * 8]);
        uint32_t bB = smem_u32(&sB2[(n0 + (lane & 15)) * ST_ + ((lane >> 4) & 1) * 8]);
        float C2[2][4] = {};
#pragma unroll
        for (int kt = 0; kt < 16; kt++) {
            uint32_t am[4], bf[4];
            ldsm_x4(am, aB + kt * 32);
            ldsm_x4(bf, bB + kt * 32);
            mma16816(C2[0], am, bf[0], bf[2]);
            mma16816(C2[1], am, bf[1], bf[3]);
        }
        int rowA = r0 + mg * 16 + (lane >> 2);
        float mk0 = mask[rowA], mk1 = mask[rowA + 8];
#pragma unroll
        for (int sub = 0; sub < 2; sub++) {
            int col = n0 + sub * 8 + (lane & 3) * 2;
            float b0 = ub2[col], b1 = ub2[col + 1];
            const float2 nv0 = *(const float2*)&nodes[(size_t)rowA * D_ + col];
            const float2 nv1 = *(const float2*)&nodes[(size_t)(rowA + 8) * D_ + col];
            float2 o0, o1;
            o0.x = (nv0.x + C2[sub][0] + b0) * mk0;
            o0.y = (nv0.y + C2[sub][1] + b1) * mk0;
            o1.x = (nv1.x + C2[sub][2] + b0) * mk1;
            o1.y = (nv1.y + C2[sub][3] + b1) * mk1;
            *(float2*)&out[(size_t)rowA * D_ + col]       = o0;
            *(float2*)&out[(size_t)(rowA + 8) * D_ + col] = o1;
        }
    }
}

// ---------------- launch ----------------
extern "C" void kernel_launch(void* const* d_in, const int* in_sizes, int n_in,
                              void* d_out, int out_size) {
    const float* nodes = (const float*)d_in[0];
    const float* mask  = (const float*)d_in[1];
    const float* ln_g  = (const float*)d_in[2];
    const float* ln_b  = (const float*)d_in[3];
    const float* mw1   = (const float*)d_in[4];
    const float* mb1   = (const float*)d_in[5];
    const float* mw2   = (const float*)d_in[6];
    const float* mb2   = (const float*)d_in[7];
    const float* uw1   = (const float*)d_in[8];
    const float* ub1   = (const float*)d_in[9];
    const float* uw2   = (const float*)d_in[10];
    const float* ub2   = (const float*)d_in[11];
    float* out = (float*)d_out;

    cudaFuncSetAttribute(k1_proj,  cudaFuncAttributeMaxDynamicSharedMemorySize, K1_TOT);
    cudaFuncSetAttribute(k2_main,  cudaFuncAttributeMaxDynamicSharedMemorySize, K2_TOT);
    cudaFuncSetAttribute(k3_final, cudaFuncAttributeMaxDynamicSharedMemorySize, K3_TOT);

    kw<<<192, 256>>>(mw1, mw2, uw1, uw2);
    k1_proj<<<128, 256, K1_TOT>>>(nodes, mask, ln_g, ln_b, mb1);
    k2_main<<<NSM_, 256, K2_TOT>>>(mb2, mask);
    k3_final<<<128, 512, K3_TOT>>>(nodes, mask, ub1, ub2, out);
}